// round 1
// baseline (speedup 1.0000x reference)
#include <cuda_runtime.h>
#include <cstdint>

// Problem constants
#define TT   64
#define BB   4096
#define HH   256
#define BC   16            // batch rows per CTA
#define NCTA (BB / BC)     // 256 CTAs

// __device__ scratch (no allocations allowed)
__device__ float d_WtH [HH * HH];   // W_h  transposed: [h][j]
__device__ float d_WtH2[HH * HH];   // W_h2 transposed: [h][j]
__device__ float d_emb [TT];
__device__ float d_val [TT * BB * 4];  // [t][b][c], c = {spk0,spk1,mem0,mem1}

// ---------------------------------------------------------------------------
// Prep: transpose recurrent weights, compute temporal embedding
// ---------------------------------------------------------------------------
__global__ void prep_kernel(const float* __restrict__ W_h,
                            const float* __restrict__ W_h2)
{
    int idx = blockIdx.x * 256 + threadIdx.x;   // 0 .. 65535
    int h = idx >> 8, j = idx & 255;
    d_WtH [idx] = W_h [j * HH + h];
    d_WtH2[idx] = W_h2[j * HH + h];
    if (blockIdx.x == 0 && threadIdx.x < TT) {
        int t = threadIdx.x;
        // center = 32, sigma = 6.4 ; min at pos 0, max (=1) at pos 32
        float p  = ((float)t - 32.0f) / 6.4f;
        float e  = expf(-0.5f * p * p);
        float e0 = expf(-0.5f * 25.0f);        // ((0-32)/6.4)^2 = 25
        d_emb[t] = (e - e0) / (1.0f - e0);
    }
}

// ---------------------------------------------------------------------------
// Main recurrent kernel: full T=64 loop, one CTA per 16 batch rows.
// Thread j = neuron index; per-thread register arrays hold membranes for the
// 16 batch rows. Spikes staged in smem (float) for the dense fp32 GEMMs.
// ---------------------------------------------------------------------------
__global__ __launch_bounds__(256, 2) void snn_main_kernel(
    const float* __restrict__ x,
    const float* __restrict__ W_in,  const float* __restrict__ b_in,
    const float* __restrict__ beta_in, const float* __restrict__ thr_in,
    const float* __restrict__ b_h,   const float* __restrict__ beta_h, const float* __restrict__ thr_h,
    const float* __restrict__ b_h2,  const float* __restrict__ beta_h2, const float* __restrict__ thr_h2,
    const float* __restrict__ W_out, const float* __restrict__ b_out, const float* __restrict__ beta_out)
{
    __shared__ float xs[BC * 3];
    __shared__ float sA[BC][HH];
    __shared__ float sB[BC][HH];
    __shared__ float red[BC][2][8];

    const int tid   = threadIdx.x;
    const int j     = tid;
    const int bbase = blockIdx.x * BC;
    const int lane  = tid & 31;
    const int warp  = tid >> 5;

    // per-neuron constants
    const float Wi0 = W_in[j * 3 + 0], Wi1 = W_in[j * 3 + 1], Wi2 = W_in[j * 3 + 2];
    const float bin = b_in[j];
    const float betaIn = fminf(fmaxf(beta_in[j], 0.f), 1.f);
    const float thrIn  = thr_in[j];
    const float bH     = b_h[j];
    const float betaH  = fminf(fmaxf(beta_h[j], 0.f), 1.f);
    const float thrH   = thr_h[j];
    const float bH2    = b_h2[j];
    const float betaH2 = fminf(fmaxf(beta_h2[j], 0.f), 1.f);
    const float thrH2  = thr_h2[j];
    const float Wo0 = W_out[0 * HH + j];
    const float Wo1 = W_out[1 * HH + j];

    float m1[BC], m2[BC], m4[BC], cur[BC];
#pragma unroll
    for (int b = 0; b < BC; ++b) { m1[b] = 0.f; m2[b] = 0.f; m4[b] = 0.f; }

    // output-layer finisher threads (tid < 32): (b, o) = (tid>>1, tid&1)
    float m3r = 0.f, betaOutC = 0.f, bo = 0.f;
    int fb = 0, fo = 0;
    if (tid < 2 * BC) {
        fb = tid >> 1; fo = tid & 1;
        betaOutC = fminf(fmaxf(beta_out[fo], 0.f), 1.f);
        bo = b_out[fo];
    }

    for (int t = 0; t < TT; ++t) {
        __syncthreads();   // protect xs/sA/red from previous iteration readers
        if (tid < BC * 3)
            xs[tid] = x[((size_t)t * BB + bbase) * 3 + tid];
        const float embt = d_emb[t];
        __syncthreads();

        // ---- layer 1 (input LIF): cur = emb * (x @ W_in^T) + b_in ----
#pragma unroll
        for (int b = 0; b < BC; ++b) {
            float c1 = embt * (xs[b * 3] * Wi0 + xs[b * 3 + 1] * Wi1 + xs[b * 3 + 2] * Wi2) + bin;
            float mo = m1[b];
            float mn = betaIn * mo + c1 - ((mo > thrIn) ? thrIn : 0.f);
            m1[b] = mn;
            sA[b][j] = (mn > thrIn) ? 1.f : 0.f;
        }
        __syncthreads();

        // ---- layer 2: cur = s1 @ W_h^T + b_h ; LIF ----
#pragma unroll
        for (int b = 0; b < BC; ++b) cur[b] = bH;
        {
            const float* wbase = d_WtH + j;
#pragma unroll 2
            for (int h4 = 0; h4 < HH / 4; ++h4) {
                const float* wp = wbase + h4 * 4 * HH;
                float w0 = wp[0], w1 = wp[HH], w2 = wp[2 * HH], w3 = wp[3 * HH];
#pragma unroll
                for (int b = 0; b < BC; ++b) {
                    float4 s = *(const float4*)&sA[b][h4 * 4];
                    cur[b] += w0 * s.x + w1 * s.y + w2 * s.z + w3 * s.w;
                }
            }
        }
#pragma unroll
        for (int b = 0; b < BC; ++b) {
            float mo = m2[b];
            float mn = betaH * mo + cur[b] - ((mo > thrH) ? thrH : 0.f);
            m2[b] = mn;
            sB[b][j] = (mn > thrH) ? 1.f : 0.f;
        }
        __syncthreads();

        // ---- layer 3: cur = s2 @ W_h2^T + b_h2 ; LIF ; spike kept in cur[] ----
#pragma unroll
        for (int b = 0; b < BC; ++b) cur[b] = bH2;
        {
            const float* wbase = d_WtH2 + j;
#pragma unroll 2
            for (int h4 = 0; h4 < HH / 4; ++h4) {
                const float* wp = wbase + h4 * 4 * HH;
                float w0 = wp[0], w1 = wp[HH], w2 = wp[2 * HH], w3 = wp[3 * HH];
#pragma unroll
                for (int b = 0; b < BC; ++b) {
                    float4 s = *(const float4*)&sB[b][h4 * 4];
                    cur[b] += w0 * s.x + w1 * s.y + w2 * s.z + w3 * s.w;
                }
            }
        }
#pragma unroll
        for (int b = 0; b < BC; ++b) {
            float mo = m4[b];
            float mn = betaH2 * mo + cur[b] - ((mo > thrH2) ? thrH2 : 0.f);
            m4[b] = mn;
            cur[b] = (mn > thrH2) ? 1.f : 0.f;   // s4 spike
        }

        // ---- output layer: cur_out[b][o] = s4 @ W_out^T  (warp-shuffle reduce) ----
#pragma unroll
        for (int b = 0; b < BC; ++b) {
            float v  = cur[b];
            float p0 = v * Wo0;
            float p1 = v * Wo1;
#pragma unroll
            for (int off = 16; off > 0; off >>= 1) {
                p0 += __shfl_down_sync(0xffffffffu, p0, off);
                p1 += __shfl_down_sync(0xffffffffu, p1, off);
            }
            if (lane == 0) { red[b][0][warp] = p0; red[b][1][warp] = p1; }
        }
        __syncthreads();

        // ---- leaky integrator (no reset), record spk & mem to d_val ----
        if (tid < 2 * BC) {
            float co = bo;
#pragma unroll
            for (int w = 0; w < 8; ++w) co += red[fb][fo][w];
            m3r = betaOutC * m3r + co;
            float spk = (m3r > 1.0f) ? 1.f : 0.f;
            size_t base = ((size_t)t * BB + bbase + fb) * 4;
            d_val[base + fo]     = spk;
            d_val[base + 2 + fo] = m3r;
        }
    }
}

// ---------------------------------------------------------------------------
// Final projection. Reference does reshape(B, T*4) on a [T,B,4] array, which
// interleaves time/batch: flat layout of d_val IS the reshaped matrix.
// out[row, o] = b_pred[o] + sum_col d_val_flat[row*256 + col] * W_pred[o*256+col]
// ---------------------------------------------------------------------------
__global__ void proj_kernel(const float* __restrict__ W_pred,
                            const float* __restrict__ b_pred,
                            float* __restrict__ out)
{
    int row  = blockIdx.x * 8 + (threadIdx.x >> 5);
    int lane = threadIdx.x & 31;
    const float* v = d_val + (size_t)row * 256;
    float p0 = 0.f, p1 = 0.f;
#pragma unroll
    for (int c = lane; c < 256; c += 32) {
        float vv = v[c];
        p0 += vv * W_pred[c];
        p1 += vv * W_pred[256 + c];
    }
#pragma unroll
    for (int off = 16; off > 0; off >>= 1) {
        p0 += __shfl_down_sync(0xffffffffu, p0, off);
        p1 += __shfl_down_sync(0xffffffffu, p1, off);
    }
    if (lane == 0) {
        out[row * 2 + 0] = p0 + b_pred[0];
        out[row * 2 + 1] = p1 + b_pred[1];
    }
}

// ---------------------------------------------------------------------------
extern "C" void kernel_launch(void* const* d_in, const int* in_sizes, int n_in,
                              void* d_out, int out_size)
{
    const float* x       = (const float*)d_in[0];
    const float* W_in    = (const float*)d_in[1];
    const float* b_in    = (const float*)d_in[2];
    const float* beta_in = (const float*)d_in[3];
    const float* thr_in  = (const float*)d_in[4];
    const float* W_h     = (const float*)d_in[5];
    const float* b_h     = (const float*)d_in[6];
    const float* beta_h  = (const float*)d_in[7];
    const float* thr_h   = (const float*)d_in[8];
    const float* W_h2    = (const float*)d_in[9];
    const float* b_h2    = (const float*)d_in[10];
    const float* beta_h2 = (const float*)d_in[11];
    const float* thr_h2  = (const float*)d_in[12];
    const float* W_out   = (const float*)d_in[13];
    const float* b_out   = (const float*)d_in[14];
    const float* beta_out= (const float*)d_in[15];
    const float* W_pred  = (const float*)d_in[16];
    const float* b_pred  = (const float*)d_in[17];
    float* out = (float*)d_out;

    prep_kernel<<<256, 256>>>(W_h, W_h2);
    snn_main_kernel<<<NCTA, 256>>>(x, W_in, b_in, beta_in, thr_in,
                                   b_h, beta_h, thr_h,
                                   b_h2, beta_h2, thr_h2,
                                   W_out, b_out, beta_out);
    proj_kernel<<<BB / 8, 256>>>(W_pred, b_pred, out);
}

// round 2
// speedup vs baseline: 4.9214x; 4.9214x over previous
#include <cuda_runtime.h>
#include <cuda_fp16.h>
#include <cstdint>

// Problem constants
#define TT   64
#define BB   4096
#define HH   256
#define BC   32            // batch rows per CTA
#define NCTA (BB / BC)     // 128 CTAs
#define SA_STRIDE 264      // halves per spike-matrix row (256 + 8 pad, 528B)

// __device__ scratch (no allocations allowed)
__device__ float d_emb [TT];
__device__ float d_val [TT * BB * 4];      // [t][b][c], c = {spk0,spk1,mem0,mem1}
// Packed weight fragments: idx = (l*2+s)*16384 + kt*1024 + ntg*32 + lane
//   l: 0=W_h (layer2), 1=W_h2 (layer3); s: 0=hi, 1=lo(*2048)
//   Each uint2 = 4 fp16 = the B-fragment data for one lane of mma.m16n8k16
__device__ uint2 d_Wpack[2 * 2 * 16 * 32 * 32];   // 512 KB

// ---------------------------------------------------------------------------
// Prep: pack split-fp16 weight fragments + temporal embedding
// ---------------------------------------------------------------------------
__global__ void prep_kernel(const float* __restrict__ W_h,
                            const float* __restrict__ W_h2)
{
    int idx = blockIdx.x * 256 + threadIdx.x;     // 0 .. 65535
    int lane = idx & 31;
    int ntg  = (idx >> 5) & 31;
    int kt   = (idx >> 10) & 15;
    int s    = (idx >> 14) & 1;
    int l    = (idx >> 15) & 1;

    const float* W = l ? W_h2 : W_h;              // [n][k] row-major
    int n  = ntg * 8 + (lane >> 2);
    int k0 = kt * 16 + (lane & 3) * 2;

    __half h[4];
#pragma unroll
    for (int i = 0; i < 4; ++i) {
        int k = k0 + (i >> 1) * 8 + (i & 1);
        float w  = W[n * HH + k];
        __half hi = __float2half_rn(w);
        if (s == 0) h[i] = hi;
        else        h[i] = __float2half_rn((w - __half2float(hi)) * 2048.0f);
    }
    uint2 v;
    v.x = (uint32_t)__half_as_ushort(h[0]) | ((uint32_t)__half_as_ushort(h[1]) << 16);
    v.y = (uint32_t)__half_as_ushort(h[2]) | ((uint32_t)__half_as_ushort(h[3]) << 16);
    d_Wpack[idx] = v;

    if (blockIdx.x == 0 && threadIdx.x < TT) {
        int t = threadIdx.x;
        float p  = ((float)t - 32.0f) / 6.4f;
        float e  = expf(-0.5f * p * p);
        float e0 = expf(-0.5f * 25.0f);
        d_emb[t] = (e - e0) / (1.0f - e0);
    }
}

// ---------------------------------------------------------------------------
// mma / ldmatrix helpers
// ---------------------------------------------------------------------------
__device__ __forceinline__ void mma16816(float* d, const uint32_t* a, uint2 b) {
    asm volatile("mma.sync.aligned.m16n8k16.row.col.f32.f16.f16.f32 "
                 "{%0,%1,%2,%3},{%4,%5,%6,%7},{%8,%9},{%0,%1,%2,%3};"
                 : "+f"(d[0]), "+f"(d[1]), "+f"(d[2]), "+f"(d[3])
                 : "r"(a[0]), "r"(a[1]), "r"(a[2]), "r"(a[3]), "r"(b.x), "r"(b.y));
}
__device__ __forceinline__ void ldm4(uint32_t* r, const __half* p) {
    uint32_t addr = (uint32_t)__cvta_generic_to_shared(p);
    asm volatile("ldmatrix.sync.aligned.m8n8.x4.shared.b16 {%0,%1,%2,%3}, [%4];"
                 : "=r"(r[0]), "=r"(r[1]), "=r"(r[2]), "=r"(r[3]) : "r"(addr));
}
__device__ __forceinline__ float clip01(float v) { return fminf(fmaxf(v, 0.f), 1.f); }

// ---------------------------------------------------------------------------
// One hidden layer: GEMM (split-fp16 HMMA) + LIF, state in fragment layout.
// TOSMEM: write spikes as fp16 to sOut; else to float sp[32].
// ---------------------------------------------------------------------------
template <bool TOSMEM>
__device__ __forceinline__ void layer_gemm(
    const __half* __restrict__ sIn, __half* __restrict__ sOut, float* sp,
    float* mstate,
    const uint2* __restrict__ packHi, const uint2* __restrict__ packLo,
    const float* __restrict__ bias, const float* __restrict__ beta,
    const float* __restrict__ thr,
    int lane, int nbase)
{
    const int g = lane >> 2, q = lane & 3;
    float dh[32], dl[32];
#pragma unroll
    for (int i = 0; i < 32; ++i) { dh[i] = 0.f; dl[i] = 0.f; }

    const __half* aBase = sIn + (size_t)(lane & 15) * SA_STRIDE + (lane >> 4) * 8;
    const int ntg0 = nbase >> 3;

#pragma unroll 2
    for (int kt = 0; kt < 16; ++kt) {
        // B fragments (coalesced LDG.64 from pre-packed layout)
        uint2 bh[4], bl[4];
#pragma unroll
        for (int nt = 0; nt < 4; ++nt) {
            int bi = kt * 1024 + (ntg0 + nt) * 32 + lane;
            bh[nt] = __ldg(packHi + bi);
            bl[nt] = __ldg(packLo + bi);
        }
        // A fragments via ldmatrix
        uint32_t a[2][4];
#pragma unroll
        for (int mt = 0; mt < 2; ++mt)
            ldm4(a[mt], aBase + mt * 16 * SA_STRIDE + kt * 16);
        // MMAs
#pragma unroll
        for (int nt = 0; nt < 4; ++nt)
#pragma unroll
            for (int mt = 0; mt < 2; ++mt) {
                mma16816(&dh[(mt * 4 + nt) * 4], a[mt], bh[nt]);
                mma16816(&dl[(mt * 4 + nt) * 4], a[mt], bl[nt]);
            }
    }

    // LIF in fragment layout
#pragma unroll
    for (int mt = 0; mt < 2; ++mt)
#pragma unroll
        for (int nt = 0; nt < 4; ++nt) {
            int n0 = nbase + nt * 8 + q * 2;
            float2 bb = *(const float2*)(bias + n0);
            float2 be = *(const float2*)(beta + n0);
            float2 th = *(const float2*)(thr  + n0);
            float be0 = clip01(be.x), be1 = clip01(be.y);
#pragma unroll
            for (int rh = 0; rh < 2; ++rh) {
                int i0 = (mt * 4 + nt) * 4 + rh * 2;
                float cur0 = dh[i0]     + dl[i0]     * (1.f / 2048.f) + bb.x;
                float cur1 = dh[i0 + 1] + dl[i0 + 1] * (1.f / 2048.f) + bb.y;
                float mo0 = mstate[i0], mo1 = mstate[i0 + 1];
                float mn0 = be0 * mo0 + cur0 - ((mo0 > th.x) ? th.x : 0.f);
                float mn1 = be1 * mo1 + cur1 - ((mo1 > th.y) ? th.y : 0.f);
                mstate[i0] = mn0; mstate[i0 + 1] = mn1;
                float s0 = (mn0 > th.x) ? 1.f : 0.f;
                float s1 = (mn1 > th.y) ? 1.f : 0.f;
                if (TOSMEM) {
                    int row = mt * 16 + g + rh * 8;
                    *(__half2*)(sOut + (size_t)row * SA_STRIDE + n0) =
                        __floats2half2_rn(s0, s1);
                } else {
                    sp[i0] = s0; sp[i0 + 1] = s1;
                }
            }
        }
}

// ---------------------------------------------------------------------------
// Main recurrent kernel: T=64 loop, one CTA per 32 batch rows, 8 warps.
// ---------------------------------------------------------------------------
__global__ __launch_bounds__(256, 1) void snn_main_kernel(
    const float* __restrict__ x,
    const float* __restrict__ W_in,  const float* __restrict__ b_in,
    const float* __restrict__ beta_in, const float* __restrict__ thr_in,
    const float* __restrict__ b_h,   const float* __restrict__ beta_h, const float* __restrict__ thr_h,
    const float* __restrict__ b_h2,  const float* __restrict__ beta_h2, const float* __restrict__ thr_h2,
    const float* __restrict__ W_out, const float* __restrict__ b_out, const float* __restrict__ beta_out)
{
    __shared__ __align__(16) __half sA[BC * SA_STRIDE];
    __shared__ __align__(16) __half sB[BC * SA_STRIDE];
    __shared__ float xs[2][BC * 3];
    __shared__ float red[BC][2][8];

    const int tid   = threadIdx.x;
    const int warp  = tid >> 5;
    const int lane  = tid & 31;
    const int g     = lane >> 2, q = lane & 3;
    const int bbase = blockIdx.x * BC;
    const int nbase = warp * 32;

    // layer-1 per-neuron constants (thread = neuron j)
    const int   j   = tid;
    const float Wi0 = W_in[j * 3 + 0], Wi1 = W_in[j * 3 + 1], Wi2 = W_in[j * 3 + 2];
    const float bin = b_in[j];
    const float betaIn = clip01(beta_in[j]);
    const float thrIn  = thr_in[j];

    float m1[BC], m2[32], m4[32];
#pragma unroll
    for (int b = 0; b < BC; ++b) m1[b] = 0.f;
#pragma unroll
    for (int i = 0; i < 32; ++i) { m2[i] = 0.f; m4[i] = 0.f; }

    // output-layer finisher (tid < 64): (b, o) = (tid>>1, tid&1)
    float m3r = 0.f, betaOutC = 0.f, bo = 0.f;
    const int fb = tid >> 1, fo = tid & 1;
    if (tid < 2 * BC) {
        betaOutC = clip01(beta_out[fo]);
        bo = b_out[fo];
    }

    const uint2* packL2h = d_Wpack;               // layer2 hi
    const uint2* packL2l = d_Wpack + 16384;       // layer2 lo
    const uint2* packL3h = d_Wpack + 32768;       // layer3 hi
    const uint2* packL3l = d_Wpack + 49152;       // layer3 lo

    // preload x(t=0)
    float xreg = 0.f;
    if (tid < BC * 3) xreg = x[(size_t)bbase * 3 + tid];

#pragma unroll 1
    for (int t = 0; t < TT; ++t) {
        if (tid < BC * 3) xs[t & 1][tid] = xreg;
        __syncthreads();                           // xs visible; prev-step smem reads done
        if (tid < BC * 3 && t + 1 < TT)
            xreg = x[((size_t)(t + 1) * BB + bbase) * 3 + tid];

        const float embt = d_emb[t];
        const float* xv = xs[t & 1];

        // ---- layer 1 (input LIF), write spikes to sA ----
#pragma unroll
        for (int b = 0; b < BC; ++b) {
            float c1 = embt * (xv[b * 3] * Wi0 + xv[b * 3 + 1] * Wi1 + xv[b * 3 + 2] * Wi2) + bin;
            float mo = m1[b];
            float mn = betaIn * mo + c1 - ((mo > thrIn) ? thrIn : 0.f);
            m1[b] = mn;
            sA[b * SA_STRIDE + j] = __float2half_rn((mn > thrIn) ? 1.f : 0.f);
        }
        __syncthreads();                           // sA ready

        // ---- layer 2: HMMA GEMM + LIF -> sB ----
        layer_gemm<true>(sA, sB, nullptr, m2, packL2h, packL2l,
                         b_h, beta_h, thr_h, lane, nbase);
        __syncthreads();                           // sB ready

        // ---- layer 3: HMMA GEMM + LIF -> spikes in regs ----
        float sp[32];
        layer_gemm<false>(sB, nullptr, sp, m4, packL3h, packL3l,
                          b_h2, beta_h2, thr_h2, lane, nbase);

        // ---- output partials: reduce this warp's n-range ----
#pragma unroll
        for (int mt = 0; mt < 2; ++mt)
#pragma unroll
            for (int rh = 0; rh < 2; ++rh) {
                float p0 = 0.f, p1 = 0.f;
#pragma unroll
                for (int nt = 0; nt < 4; ++nt) {
                    int n0 = nbase + nt * 8 + q * 2;
                    float2 w0 = *(const float2*)(W_out + n0);
                    float2 w1 = *(const float2*)(W_out + HH + n0);
                    int i0 = (mt * 4 + nt) * 4 + rh * 2;
                    p0 += sp[i0] * w0.x + sp[i0 + 1] * w0.y;
                    p1 += sp[i0] * w1.x + sp[i0 + 1] * w1.y;
                }
                p0 += __shfl_xor_sync(0xffffffffu, p0, 1);
                p0 += __shfl_xor_sync(0xffffffffu, p0, 2);
                p1 += __shfl_xor_sync(0xffffffffu, p1, 1);
                p1 += __shfl_xor_sync(0xffffffffu, p1, 2);
                if (q == 0) {
                    int row = mt * 16 + g + rh * 8;
                    red[row][0][warp] = p0;
                    red[row][1][warp] = p1;
                }
            }
        __syncthreads();                           // red ready

        // ---- leaky integrator (no reset), record spk & mem ----
        if (tid < 2 * BC) {
            float co = bo;
#pragma unroll
            for (int w = 0; w < 8; ++w) co += red[fb][fo][w];
            m3r = betaOutC * m3r + co;
            float spk = (m3r > 1.0f) ? 1.f : 0.f;
            size_t base = ((size_t)t * BB + bbase + fb) * 4;
            d_val[base + fo]     = spk;
            d_val[base + 2 + fo] = m3r;
        }
    }
}

// ---------------------------------------------------------------------------
// Final projection: flat d_val IS the reshaped [B, T*4] matrix.
// ---------------------------------------------------------------------------
__global__ void proj_kernel(const float* __restrict__ W_pred,
                            const float* __restrict__ b_pred,
                            float* __restrict__ out)
{
    int row  = blockIdx.x * 8 + (threadIdx.x >> 5);
    int lane = threadIdx.x & 31;
    const float* v = d_val + (size_t)row * 256;
    float p0 = 0.f, p1 = 0.f;
#pragma unroll
    for (int c = lane; c < 256; c += 32) {
        float vv = v[c];
        p0 += vv * W_pred[c];
        p1 += vv * W_pred[256 + c];
    }
#pragma unroll
    for (int off = 16; off > 0; off >>= 1) {
        p0 += __shfl_down_sync(0xffffffffu, p0, off);
        p1 += __shfl_down_sync(0xffffffffu, p1, off);
    }
    if (lane == 0) {
        out[row * 2 + 0] = p0 + b_pred[0];
        out[row * 2 + 1] = p1 + b_pred[1];
    }
}

// ---------------------------------------------------------------------------
extern "C" void kernel_launch(void* const* d_in, const int* in_sizes, int n_in,
                              void* d_out, int out_size)
{
    const float* x       = (const float*)d_in[0];
    const float* W_in    = (const float*)d_in[1];
    const float* b_in    = (const float*)d_in[2];
    const float* beta_in = (const float*)d_in[3];
    const float* thr_in  = (const float*)d_in[4];
    const float* W_h     = (const float*)d_in[5];
    const float* b_h     = (const float*)d_in[6];
    const float* beta_h  = (const float*)d_in[7];
    const float* thr_h   = (const float*)d_in[8];
    const float* W_h2    = (const float*)d_in[9];
    const float* b_h2    = (const float*)d_in[10];
    const float* beta_h2 = (const float*)d_in[11];
    const float* thr_h2  = (const float*)d_in[12];
    const float* W_out   = (const float*)d_in[13];
    const float* b_out   = (const float*)d_in[14];
    const float* beta_out= (const float*)d_in[15];
    const float* W_pred  = (const float*)d_in[16];
    const float* b_pred  = (const float*)d_in[17];
    float* out = (float*)d_out;

    prep_kernel<<<256, 256>>>(W_h, W_h2);
    snn_main_kernel<<<NCTA, 256>>>(x, W_in, b_in, beta_in, thr_in,
                                   b_h, beta_h, thr_h,
                                   b_h2, beta_h2, thr_h2,
                                   W_out, b_out, beta_out);
    proj_kernel<<<BB / 8, 256>>>(W_pred, b_pred, out);
}